// round 4
// baseline (speedup 1.0000x reference)
#include <cuda_runtime.h>
#include <cstdint>

// out[b][h] = in[b][idx[h]]
// in:  (BATCH, 117) fp32
// idx: (600,) int32  <-- jax x64-disabled downcasts the "int64" randint to int32
// out: (BATCH, 600) fp32
//
// Pure HBM-bound gather. Each thread produces one float4 (4 output elems)
// per loop iteration; indices are staged in shared and fetched as int4
// (one LDS.128 per output vector). Streaming stores keep L2 for the
// reused input rows. All loop indexing is 32-bit (19.66M vectors < 2^31).

#ifndef NUM_VERBS
#define NUM_VERBS 117
#endif
#define NUM_HOIS 600
#define VECS_PER_ROW (NUM_HOIS / 4)   // 150

__global__ void __launch_bounds__(256)
scatter_verbs_kernel(const float* __restrict__ in,
                     const int* __restrict__ idx,
                     float* __restrict__ out,
                     int batch)
{
    __shared__ __align__(16) int sidx[NUM_HOIS];

    // Stage indices once per block.
    for (int i = threadIdx.x; i < NUM_HOIS; i += blockDim.x) {
        sidx[i] = idx[i];
    }
    __syncthreads();

    const int total  = batch * VECS_PER_ROW;          // 19,660,800 float4s
    const int stride = gridDim.x * blockDim.x;
    float4* __restrict__ out4 = reinterpret_cast<float4*>(out);
    const int4* __restrict__ sidx4 = reinterpret_cast<const int4*>(sidx);

    for (int g = blockIdx.x * blockDim.x + threadIdx.x; g < total; g += stride)
    {
        int row = g / VECS_PER_ROW;                   // magic-multiply, cheap
        int vec = g - row * VECS_PER_ROW;

        const float* __restrict__ inr = in + (long long)row * NUM_VERBS;
        int4 h4 = sidx4[vec];

        float4 v;
        v.x = __ldg(inr + h4.x);
        v.y = __ldg(inr + h4.y);
        v.z = __ldg(inr + h4.z);
        v.w = __ldg(inr + h4.w);

        // Streaming store: output is write-once, larger than L2.
        __stcs(&out4[g], v);
    }
}

extern "C" void kernel_launch(void* const* d_in, const int* in_sizes, int n_in,
                              void* d_out, int out_size)
{
    const float* in  = (const float*)d_in[0];
    const int*   idx = (const int*)d_in[1];
    float*       out = (float*)d_out;

    int batch = in_sizes[0] / NUM_VERBS;   // 131072

    const int threads = 256;
    const int blocks  = 2048;              // grid-stride; ~37 float4/thread
    scatter_verbs_kernel<<<blocks, threads>>>(in, idx, out, batch);
}

// round 5
// speedup vs baseline: 1.0901x; 1.0901x over previous
#include <cuda_runtime.h>
#include <cstdint>

// out[b][h] = in[b][idx[h]]
// in:  (131072, 117) fp32, idx: (600,) int32, out: (131072, 600) fp32
//
// R4 profile: L1tex = 73.9% (scattered scalar LDG gathers), DRAM = 51.9%.
// Fix: stage 64 rows per block into SHARED with coalesced loads, gather via
// the smem crossbar (handles lane-random 4B access at conflict-degree cost),
// stream float4 stores. Row stride 117 (odd) rotates row bases across banks.

#define NUM_VERBS 117
#define NUM_HOIS 600
#define VECS_PER_ROW (NUM_HOIS / 4)       // 150
#define ROWS_PER_BLK 64
#define THREADS 256
#define FLOATS_PER_BLK (ROWS_PER_BLK * NUM_VERBS)      // 7488
#define TASKS_PER_BLK (ROWS_PER_BLK * VECS_PER_ROW)    // 9600

__global__ void __launch_bounds__(THREADS)
scatter_verbs_kernel(const float* __restrict__ in,
                     const int* __restrict__ idx,
                     float* __restrict__ out)
{
    __shared__ float srow[FLOATS_PER_BLK];             // 29952 B
    __shared__ __align__(16) int sidx[NUM_HOIS];       //  2400 B

    const int tid  = threadIdx.x;
    const int row0 = blockIdx.x * ROWS_PER_BLK;

    // Stage index table (tiny, L2-hot).
    for (int i = tid; i < NUM_HOIS; i += THREADS)
        sidx[i] = idx[i];

    // Phase 1: coalesced copy of this block's 64 input rows into shared.
    const float* __restrict__ src = in + (size_t)row0 * NUM_VERBS;
    #pragma unroll 4
    for (int i = tid; i < FLOATS_PER_BLK; i += THREADS)
        srow[i] = __ldg(src + i);

    __syncthreads();

    // Phase 2: gather from shared, stream vectorized stores.
    const int4* __restrict__ sidx4 = reinterpret_cast<const int4*>(sidx);
    float4* __restrict__ out4 =
        reinterpret_cast<float4*>(out) + (size_t)row0 * VECS_PER_ROW;

    #pragma unroll 2
    for (int t = tid; t < TASKS_PER_BLK; t += THREADS) {
        int r   = t / VECS_PER_ROW;                    // magic-multiply
        int vec = t - r * VECS_PER_ROW;

        const float* __restrict__ rw = srow + r * NUM_VERBS;
        int4 h = sidx4[vec];

        float4 v;
        v.x = rw[h.x];
        v.y = rw[h.y];
        v.z = rw[h.z];
        v.w = rw[h.w];

        __stcs(&out4[t], v);                           // t == r*150 + vec
    }
}

extern "C" void kernel_launch(void* const* d_in, const int* in_sizes, int n_in,
                              void* d_out, int out_size)
{
    const float* in  = (const float*)d_in[0];
    const int*   idx = (const int*)d_in[1];
    float*       out = (float*)d_out;

    int batch  = in_sizes[0] / NUM_VERBS;              // 131072
    int blocks = batch / ROWS_PER_BLK;                 // 2048 (exact)

    scatter_verbs_kernel<<<blocks, THREADS>>>(in, idx, out);
}

// round 7
// speedup vs baseline: 1.2246x; 1.1233x over previous
#include <cuda_runtime.h>
#include <cstdint>

// out[b][h] = in[b][idx[h]]
// in: (131072, 117) fp32, idx: (600,) int32, out: (131072, 600) fp32
//
// R5 profile: L1tex=72.4% bound. Budget per warp-iter was ~23.6 cyc:
// gather LDS 13.6 (irreducible conflicts) + sidx LDS.128 4 + STG 4 + staging 2.
// This version removes the recurring index LDS (indices live in registers,
// fixed per thread for the whole block) and the div/mod, and restores full
// occupancy with 32-row tiles.

#define NUM_VERBS 117
#define VECS_PER_ROW 150                  // 600 / 4
#define NUM_WIN 5                         // ceil(150 / 32)
#define ROWS_PER_BLK 32
#define THREADS 256                       // 8 warps
#define WARPS 8
#define FLOATS_PER_BLK (ROWS_PER_BLK * NUM_VERBS)   // 3744 (divisible by 4)

__global__ void __launch_bounds__(THREADS)
scatter_verbs_kernel(const float* __restrict__ in,
                     const int* __restrict__ idx,
                     float* __restrict__ out)
{
    __shared__ float srow[FLOATS_PER_BLK];          // 14976 B, stride 117 (21 mod 32)

    const int tid  = threadIdx.x;
    const int lane = tid & 31;
    const int w    = tid >> 5;
    const int row0 = blockIdx.x * ROWS_PER_BLK;

    // Load this thread's gather indices ONCE (L2-hot, 150 int4 total).
    const int4* __restrict__ idx4 = reinterpret_cast<const int4*>(idx);
    int4 hreg[NUM_WIN];
    #pragma unroll
    for (int win = 0; win < NUM_WIN; win++) {
        int v = win * 32 + lane;
        hreg[win] = (v < VECS_PER_ROW) ? __ldg(&idx4[v]) : make_int4(0, 0, 0, 0);
    }

    // Stage 32 input rows into shared, vectorized + coalesced.
    {
        const float4* __restrict__ src4 =
            reinterpret_cast<const float4*>(in + (size_t)row0 * NUM_VERBS);
        float4* __restrict__ dst4 = reinterpret_cast<float4*>(srow);
        #pragma unroll
        for (int i = tid; i < FLOATS_PER_BLK / 4; i += THREADS)
            dst4[i] = __ldg(&src4[i]);
    }
    __syncthreads();

    // Gather + stream stores. Warp w owns rows w, w+8, w+16, w+24.
    float4* __restrict__ out4 =
        reinterpret_cast<float4*>(out) + (size_t)row0 * VECS_PER_ROW;

    #pragma unroll
    for (int r = 0; r < ROWS_PER_BLK / WARPS; r++) {
        const int row = r * WARPS + w;
        const float* __restrict__ rw = srow + row * NUM_VERBS;
        float4* __restrict__ orow = out4 + row * VECS_PER_ROW;

        #pragma unroll
        for (int win = 0; win < NUM_WIN; win++) {
            int v = win * 32 + lane;
            if (v < VECS_PER_ROW) {
                int4 h = hreg[win];
                float4 o;
                o.x = rw[h.x];
                o.y = rw[h.y];
                o.z = rw[h.z];
                o.w = rw[h.w];
                __stcs(&orow[v], o);
            }
        }
    }
}

extern "C" void kernel_launch(void* const* d_in, const int* in_sizes, int n_in,
                              void* d_out, int out_size)
{
    const float* in  = (const float*)d_in[0];
    const int*   idx = (const int*)d_in[1];
    float*       out = (float*)d_out;

    int batch  = in_sizes[0] / NUM_VERBS;           // 131072
    int blocks = batch / ROWS_PER_BLK;              // 4096 (exact)

    scatter_verbs_kernel<<<blocks, THREADS>>>(in, idx, out);
}